// round 9
// baseline (speedup 1.0000x reference)
#include <cuda_runtime.h>
#include <cuda_bf16.h>
#include <cstdint>

#define N_P   200000
#define N_A   100000
#define D_MP  64
#define E_NNZ 1200000
#define F_P   256
#define F_A   128

// ===========================================================================
// Static scratch
// ===========================================================================
__device__ __align__(16) float g_bufP [(size_t)N_P * D_MP];   // zp, later g
__device__ __align__(16) float g_bufA1[(size_t)N_A * D_MP];   // za
__device__ __align__(16) float g_bufA2[(size_t)N_A * D_MP];   // h, later h2

// Pre-split W images (hi/lo bf16x2 pairs), laid out per 32-k chunk to match
// the GEMM smem image: dst[chunk*1024 + idx], idx -> (nn = idx&63, kp = idx>>6)
__device__ __align__(16) uint2 g_WsplitP[(F_P / 32) * 1024];
__device__ __align__(16) uint2 g_WsplitA[(F_A / 32) * 1024];

// CSR scratch (packed edges: .x = col, .y = val bits)
__device__ int   g_pa_ptr[N_A + 1];
__device__ int   g_ap_ptr[N_P + 1];
__device__ __align__(16) int2 g_pa_edge[E_NNZ];
__device__ __align__(16) int2 g_ap_edge[E_NNZ];
__device__ int   g_cnt[2 * (N_P + N_A)];
__device__ int   g_bsumA[128];
__device__ int   g_bsumP[128];

// ===========================================================================
// bf16 split helpers
// ===========================================================================
__device__ __forceinline__ uint2 split_pack(float a, float b) {
    float fa = __bfloat162float(__float2bfloat16_rn(a));
    float fb = __bfloat162float(__float2bfloat16_rn(b));
    uint32_t hi, lo;
    asm("cvt.rn.bf16x2.f32 %0, %1, %2;" : "=r"(hi) : "f"(fb), "f"(fa));
    asm("cvt.rn.bf16x2.f32 %0, %1, %2;" : "=r"(lo) : "f"(b - fb), "f"(a - fa));
    return make_uint2(hi, lo);
}

__device__ __forceinline__ void mma_bf16(float* d, const uint32_t* a, const uint32_t* b) {
    asm volatile("mma.sync.aligned.m16n8k16.row.col.f32.bf16.bf16.f32 "
                 "{%0,%1,%2,%3}, {%4,%5,%6,%7}, {%8,%9}, {%0,%1,%2,%3};"
                 : "+f"(d[0]), "+f"(d[1]), "+f"(d[2]), "+f"(d[3])
                 : "r"(a[0]), "r"(a[1]), "r"(a[2]), "r"(a[3]),
                   "r"(b[0]), "r"(b[1]));
}

// ===========================================================================
// Prep: split W into the chunked smem image layout (done once, tiny)
// ===========================================================================
__global__ void prep_W(const float* __restrict__ W, uint2* __restrict__ dst, int F) {
    int i = blockIdx.x * blockDim.x + threadIdx.x;
    int total = (F / 32) * 1024;
    if (i >= total) return;
    int chunk = i >> 10;
    int idx   = i & 1023;
    int nn = idx & 63;
    int kp = idx >> 6;
    int k  = chunk * 32 + kp * 2;
    float w0 = W[(size_t)k * 64 + nn];
    float w1 = W[(size_t)(k + 1) * 64 + nn];
    dst[i] = split_pack(w0, w1);
}

// ===========================================================================
// Tensor-core GEMM via mma.sync m16n8k16 (3x bf16 split, ~1e-5 accuracy)
// 256 threads; block tile 128x64; warp tile 32x32; 3 CTAs/SM target.
// W arrives pre-split (straight copy); x split on stage.
// ===========================================================================
template<int F>
__global__ __launch_bounds__(256, 3) void gemm_bf16x3(const float* __restrict__ x,
                                                      const uint2* __restrict__ Wsp,
                                                      float* __restrict__ out, int n) {
    __shared__ uint2 ws[64 * 20];      // W chunk image
    __shared__ uint2 xs[128 * 20];     // x chunk image

    const int t    = threadIdx.x;
    const int lane = t & 31;
    const int wid  = t >> 5;
    const int wm   = wid >> 1;
    const int wn   = wid & 1;
    const int tig  = lane & 3;
    const int gid  = lane >> 2;
    const int row0 = blockIdx.x * 128;

    float acc[2][4][4];
    #pragma unroll
    for (int mt = 0; mt < 2; mt++)
        #pragma unroll
        for (int nt = 0; nt < 4; nt++)
            #pragma unroll
            for (int q = 0; q < 4; q++) acc[mt][nt][q] = 0.f;

    for (int kc = 0; kc < F; kc += 32) {
        __syncthreads();
        // stage W chunk: straight copy of pre-split image
        const uint2* src = Wsp + (kc >> 5) * 1024;
        #pragma unroll
        for (int j = 0; j < 4; j++) {
            int idx = j * 256 + t;
            int nn  = idx & 63;
            int kp  = idx >> 6;
            ws[nn * 20 + kp] = __ldg(src + idx);
        }
        // stage x chunk: 128 rows x 16 kpairs, split on the fly
        #pragma unroll
        for (int j = 0; j < 8; j++) {
            int idx = j * 256 + t;
            int r   = idx >> 4;
            int kp  = idx & 15;
            int grow = row0 + r;
            float2 v = make_float2(0.f, 0.f);
            if (grow < n)
                v = *(const float2*)(x + (size_t)grow * F + kc + kp * 2);
            xs[r * 20 + kp] = split_pack(v.x, v.y);
        }
        __syncthreads();

        #pragma unroll
        for (int ks = 0; ks < 2; ks++) {
            const int p0 = ks * 8 + tig;
            const int p1 = p0 + 4;

            uint32_t ah[2][4], al[2][4];
            #pragma unroll
            for (int mt = 0; mt < 2; mt++) {
                int r0 = wm * 32 + mt * 16 + gid;
                uint2 qa0 = xs[r0 * 20 + p0];
                uint2 qa1 = xs[(r0 + 8) * 20 + p0];
                uint2 qa2 = xs[r0 * 20 + p1];
                uint2 qa3 = xs[(r0 + 8) * 20 + p1];
                ah[mt][0] = qa0.x; ah[mt][1] = qa1.x; ah[mt][2] = qa2.x; ah[mt][3] = qa3.x;
                al[mt][0] = qa0.y; al[mt][1] = qa1.y; al[mt][2] = qa2.y; al[mt][3] = qa3.y;
            }

            #pragma unroll
            for (int nt = 0; nt < 4; nt++) {
                int nn = wn * 32 + nt * 8 + gid;
                uint2 qb0 = ws[nn * 20 + p0];
                uint2 qb1 = ws[nn * 20 + p1];
                uint32_t bh[2] = {qb0.x, qb1.x};
                uint32_t bl[2] = {qb0.y, qb1.y};
                #pragma unroll
                for (int mt = 0; mt < 2; mt++) {
                    mma_bf16(acc[mt][nt], ah[mt], bh);
                    mma_bf16(acc[mt][nt], al[mt], bh);
                    mma_bf16(acc[mt][nt], ah[mt], bl);
                }
            }
        }
    }

    // Epilogue
    #pragma unroll
    for (int mt = 0; mt < 2; mt++) {
        #pragma unroll
        for (int half = 0; half < 2; half++) {
            int grow = row0 + wm * 32 + mt * 16 + gid + half * 8;
            if (grow < n) {
                float* o = out + (size_t)grow * D_MP + wn * 32 + tig * 2;
                #pragma unroll
                for (int nt = 0; nt < 4; nt++) {
                    float2 v = half ? make_float2(acc[mt][nt][2], acc[mt][nt][3])
                                    : make_float2(acc[mt][nt][0], acc[mt][nt][1]);
                    *(float2*)(o + nt * 8) = v;
                }
            }
        }
    }
}

// ===========================================================================
// CSR build
// ===========================================================================
__global__ void hist_dual(const int* __restrict__ rowA, const int* __restrict__ rowP,
                          int* __restrict__ cntA, int* __restrict__ cntP) {
    int i = blockIdx.x * blockDim.x + threadIdx.x;
    if (i < E_NNZ) {
        atomicAdd(&cntA[rowA[i]], 1);
    } else if (i < 2 * E_NNZ) {
        atomicAdd(&cntP[rowP[i - E_NNZ]], 1);
    }
}

#define SCAN_CHUNK 2048

__global__ void scan_pass1_dual(const int* __restrict__ cntA, int* __restrict__ bsA, int nA,
                                const int* __restrict__ cntP, int* __restrict__ bsP, int nP,
                                int nbA) {
    __shared__ int sh[256];
    const int* cnt = (blockIdx.x < nbA) ? cntA : cntP;
    int*       bs  = (blockIdx.x < nbA) ? bsA  : bsP;
    int        n   = (blockIdx.x < nbA) ? nA   : nP;
    int        blk = (blockIdx.x < nbA) ? blockIdx.x : blockIdx.x - nbA;
    int base = blk * SCAN_CHUNK;
    int t = threadIdx.x;
    int s = 0;
    #pragma unroll
    for (int j = 0; j < 8; j++) {
        int i = base + t * 8 + j;
        if (i < n) s += cnt[i];
    }
    sh[t] = s;
    __syncthreads();
    for (int off = 128; off > 0; off >>= 1) {
        if (t < off) sh[t] += sh[t + off];
        __syncthreads();
    }
    if (t == 0) bs[blk] = sh[0];
}

__global__ void scan_pass2_dual(int* __restrict__ bsA, int nbA,
                                int* __restrict__ bsP, int nbP) {
    __shared__ int sh[128];
    int* bs = blockIdx.x ? bsP : bsA;
    int nb  = blockIdx.x ? nbP : nbA;
    int t = threadIdx.x;
    int v = (t < nb) ? bs[t] : 0;
    sh[t] = v;
    __syncthreads();
    for (int off = 1; off < 128; off <<= 1) {
        int xx = (t >= off) ? sh[t - off] : 0;
        __syncthreads();
        sh[t] += xx;
        __syncthreads();
    }
    if (t < nb) bs[t] = sh[t] - v;
}

__global__ void scan_pass3_dual(const int* __restrict__ cntA, const int* __restrict__ bsA,
                                int* __restrict__ ptrA, int nA,
                                const int* __restrict__ cntP, const int* __restrict__ bsP,
                                int* __restrict__ ptrP, int nP, int nbA) {
    __shared__ int sh[256];
    const int* cnt = (blockIdx.x < nbA) ? cntA : cntP;
    const int* bs  = (blockIdx.x < nbA) ? bsA  : bsP;
    int*       ptr = (blockIdx.x < nbA) ? ptrA : ptrP;
    int        n   = (blockIdx.x < nbA) ? nA   : nP;
    int        blk = (blockIdx.x < nbA) ? blockIdx.x : blockIdx.x - nbA;
    int base = blk * SCAN_CHUNK;
    int t = threadIdx.x;
    int v[8];
    int s = 0;
    #pragma unroll
    for (int j = 0; j < 8; j++) {
        int i = base + t * 8 + j;
        v[j] = (i < n) ? cnt[i] : 0;
        s += v[j];
    }
    sh[t] = s;
    __syncthreads();
    for (int off = 1; off < 256; off <<= 1) {
        int xx = (t >= off) ? sh[t - off] : 0;
        __syncthreads();
        sh[t] += xx;
        __syncthreads();
    }
    int ex = sh[t] - s + bs[blk];
    #pragma unroll
    for (int j = 0; j < 8; j++) {
        int i = base + t * 8 + j;
        if (i < n) {
            ptr[i] = ex;
            ex += v[j];
            if (i == n - 1) ptr[n] = ex;
        }
    }
}

__global__ void scatter_dual(const int* __restrict__ rowA, const int* __restrict__ colA,
                             const float* __restrict__ valA,
                             const int* __restrict__ ptrA, int* __restrict__ curA,
                             int2* __restrict__ edgeA,
                             const int* __restrict__ rowP, const int* __restrict__ colP,
                             const float* __restrict__ valP,
                             const int* __restrict__ ptrP, int* __restrict__ curP,
                             int2* __restrict__ edgeP) {
    int i = blockIdx.x * blockDim.x + threadIdx.x;
    if (i < E_NNZ) {
        int r = rowA[i];
        int p = ptrA[r] + atomicAdd(&curA[r], 1);
        edgeA[p] = make_int2(colA[i], __float_as_int(valA[i]));
    } else if (i < 2 * E_NNZ) {
        int j = i - E_NNZ;
        int r = rowP[j];
        int p = ptrP[r] + atomicAdd(&curP[r], 1);
        edgeP[p] = make_int2(colP[j], __float_as_int(valP[j]));
    }
}

// ===========================================================================
// CSR SpMM: warp per row, packed int2 edges, 2-way unrolled per 16-lane half
// ===========================================================================
__global__ void spmm_csr_kernel(const int* __restrict__ ptr,
                                const int2* __restrict__ edges,
                                const float* __restrict__ z,
                                float* __restrict__ out, int nrows) {
    int w = (blockIdx.x * blockDim.x + threadIdx.x) >> 5;
    if (w >= nrows) return;
    int lane = threadIdx.x & 31;
    int half = lane >> 4;
    int s    = lane & 15;

    int beg = ptr[w], end = ptr[w + 1];
    float4 acc0 = make_float4(0.f, 0.f, 0.f, 0.f);
    float4 acc1 = make_float4(0.f, 0.f, 0.f, 0.f);

    int e = beg + half;
    for (; e + 2 < end; e += 4) {
        int2 e0 = __ldg(edges + e);
        int2 e1 = __ldg(edges + e + 2);
        float v0 = __int_as_float(e0.y);
        float v1 = __int_as_float(e1.y);
        float4 z0 = __ldg((const float4*)(z + (size_t)e0.x * D_MP) + s);
        float4 z1 = __ldg((const float4*)(z + (size_t)e1.x * D_MP) + s);
        acc0.x = fmaf(v0, z0.x, acc0.x);
        acc0.y = fmaf(v0, z0.y, acc0.y);
        acc0.z = fmaf(v0, z0.z, acc0.z);
        acc0.w = fmaf(v0, z0.w, acc0.w);
        acc1.x = fmaf(v1, z1.x, acc1.x);
        acc1.y = fmaf(v1, z1.y, acc1.y);
        acc1.z = fmaf(v1, z1.z, acc1.z);
        acc1.w = fmaf(v1, z1.w, acc1.w);
    }
    if (e < end) {
        int2 e0 = __ldg(edges + e);
        float v = __int_as_float(e0.y);
        float4 zv = __ldg((const float4*)(z + (size_t)e0.x * D_MP) + s);
        acc0.x = fmaf(v, zv.x, acc0.x);
        acc0.y = fmaf(v, zv.y, acc0.y);
        acc0.z = fmaf(v, zv.z, acc0.z);
        acc0.w = fmaf(v, zv.w, acc0.w);
    }
    acc0.x += acc1.x; acc0.y += acc1.y; acc0.z += acc1.z; acc0.w += acc1.w;

    acc0.x += __shfl_xor_sync(0xffffffffu, acc0.x, 16);
    acc0.y += __shfl_xor_sync(0xffffffffu, acc0.y, 16);
    acc0.z += __shfl_xor_sync(0xffffffffu, acc0.z, 16);
    acc0.w += __shfl_xor_sync(0xffffffffu, acc0.w, 16);
    if (half == 0)
        *((float4*)(out + (size_t)w * D_MP) + s) = acc0;
}

// ===========================================================================
// Launch
// ===========================================================================
extern "C" void kernel_launch(void* const* d_in, const int* in_sizes, int n_in,
                              void* d_out, int out_size) {
    const float* x_paper  = (const float*)d_in[0];
    const float* x_author = (const float*)d_in[1];
    const float* W_paper  = (const float*)d_in[2];
    const float* W_author = (const float*)d_in[3];
    const int*   pa_row   = (const int*)  d_in[4];
    const int*   pa_col   = (const int*)  d_in[5];
    const float* pa_val   = (const float*)d_in[6];
    const int*   ap_row   = (const int*)  d_in[7];
    const int*   ap_col   = (const int*)  d_in[8];
    const float* ap_val   = (const float*)d_in[9];

    float* out       = (float*)d_out;
    float* out_pap   = out;
    float* out_papap = out + (size_t)N_P * D_MP;
    float* out_apa   = out + (size_t)2 * N_P * D_MP;

    float *bufP, *bufA1, *bufA2;
    uint2 *WspP, *WspA;
    int *pa_ptr, *ap_ptr, *cnt, *bsumA, *bsumP;
    int2 *pa_edge, *ap_edge;
    cudaGetSymbolAddress((void**)&bufP,    g_bufP);
    cudaGetSymbolAddress((void**)&bufA1,   g_bufA1);
    cudaGetSymbolAddress((void**)&bufA2,   g_bufA2);
    cudaGetSymbolAddress((void**)&WspP,    g_WsplitP);
    cudaGetSymbolAddress((void**)&WspA,    g_WsplitA);
    cudaGetSymbolAddress((void**)&pa_ptr,  g_pa_ptr);
    cudaGetSymbolAddress((void**)&ap_ptr,  g_ap_ptr);
    cudaGetSymbolAddress((void**)&pa_edge, g_pa_edge);
    cudaGetSymbolAddress((void**)&ap_edge, g_ap_edge);
    cudaGetSymbolAddress((void**)&cnt,     g_cnt);
    cudaGetSymbolAddress((void**)&bsumA,   g_bsumA);
    cudaGetSymbolAddress((void**)&bsumP,   g_bsumP);

    int* cntA = cnt;
    int* curA = cnt + N_A;
    int* cntP = cnt + 2 * N_A;
    int* curP = cnt + 2 * N_A + N_P;

    cudaMemsetAsync(cnt, 0, (size_t)2 * (N_P + N_A) * sizeof(int));

    const int HB = 256;
    const int dgrid = (2 * E_NNZ + HB - 1) / HB;
    const int nbA = (N_A + SCAN_CHUNK - 1) / SCAN_CHUNK;
    const int nbP = (N_P + SCAN_CHUNK - 1) / SCAN_CHUNK;

    // node order: capture slot (4th kernel, idx 3) = gemm P
    hist_dual<<<dgrid, HB>>>(pa_row, ap_row, cntA, cntP);                          // 0
    prep_W<<<(F_P / 32 * 1024 + 255) / 256, 256>>>(W_paper,  WspP, F_P);           // 1
    prep_W<<<(F_A / 32 * 1024 + 255) / 256, 256>>>(W_author, WspA, F_A);           // 2
    gemm_bf16x3<F_P><<<(N_P + 127) / 128, 256>>>(x_paper,  WspP, bufP,  N_P);      // 3 <- profiled
    gemm_bf16x3<F_A><<<(N_A + 127) / 128, 256>>>(x_author, WspA, bufA1, N_A);      // 4
    scan_pass1_dual<<<nbA + nbP, 256>>>(cntA, bsumA, N_A, cntP, bsumP, N_P, nbA);  // 5
    scan_pass2_dual<<<2, 128>>>(bsumA, nbA, bsumP, nbP);                           // 6
    scan_pass3_dual<<<nbA + nbP, 256>>>(cntA, bsumA, pa_ptr, N_A,
                                        cntP, bsumP, ap_ptr, N_P, nbA);            // 7
    scatter_dual<<<dgrid, HB>>>(pa_row, pa_col, pa_val, pa_ptr, curA, pa_edge,
                                ap_row, ap_col, ap_val, ap_ptr, curP, ap_edge);    // 8

    auto sblocks = [](int nrows) { return (nrows * 32 + 255) / 256; };

    // P-A-P
    spmm_csr_kernel<<<sblocks(N_A), 256>>>(pa_ptr, pa_edge, bufP,  bufA2,   N_A);
    spmm_csr_kernel<<<sblocks(N_P), 256>>>(ap_ptr, ap_edge, bufA2, out_pap, N_P);
    // P-A-P-A-P
    spmm_csr_kernel<<<sblocks(N_A), 256>>>(pa_ptr, pa_edge, out_pap, bufA2,     N_A);
    spmm_csr_kernel<<<sblocks(N_P), 256>>>(ap_ptr, ap_edge, bufA2,   out_papap, N_P);
    // A-P-A
    spmm_csr_kernel<<<sblocks(N_P), 256>>>(ap_ptr, ap_edge, bufA1, bufP,    N_P);
    spmm_csr_kernel<<<sblocks(N_A), 256>>>(pa_ptr, pa_edge, bufP,  out_apa, N_A);
}

// round 10
// speedup vs baseline: 1.2120x; 1.2120x over previous
#include <cuda_runtime.h>
#include <cuda_bf16.h>
#include <cstdint>

#define N_P   200000
#define N_A   100000
#define D_MP  64
#define E_NNZ 1200000
#define F_P   256
#define F_A   128

// ===========================================================================
// Static scratch
// ===========================================================================
__device__ __align__(16) float g_bufP [(size_t)N_P * D_MP];   // zp, later g
__device__ __align__(16) float g_bufA1[(size_t)N_A * D_MP];   // za
__device__ __align__(16) float g_bufA2[(size_t)N_A * D_MP];   // h, later h2

// Pre-split W images (hi/lo bf16x2), chunked to match the GEMM smem image
__device__ __align__(16) uint2 g_WsplitP[(F_P / 32) * 1024];
__device__ __align__(16) uint2 g_WsplitA[(F_A / 32) * 1024];

// CSR scratch (separate col/val arrays — R8 measured-best)
__device__ int   g_pa_ptr[N_A + 1];
__device__ int   g_ap_ptr[N_P + 1];
__device__ int   g_pa_ccol[E_NNZ];
__device__ float g_pa_cval[E_NNZ];
__device__ int   g_ap_ccol[E_NNZ];
__device__ float g_ap_cval[E_NNZ];
__device__ int   g_cnt[2 * (N_P + N_A)];
__device__ int   g_bsumA[128];
__device__ int   g_bsumP[128];

// ===========================================================================
// bf16 split helpers
// ===========================================================================
__device__ __forceinline__ uint2 split_pack(float a, float b) {
    float fa = __bfloat162float(__float2bfloat16_rn(a));
    float fb = __bfloat162float(__float2bfloat16_rn(b));
    uint32_t hi, lo;
    asm("cvt.rn.bf16x2.f32 %0, %1, %2;" : "=r"(hi) : "f"(fb), "f"(fa));
    asm("cvt.rn.bf16x2.f32 %0, %1, %2;" : "=r"(lo) : "f"(b - fb), "f"(a - fa));
    return make_uint2(hi, lo);
}

__device__ __forceinline__ void mma_bf16(float* d, const uint32_t* a, const uint32_t* b) {
    asm volatile("mma.sync.aligned.m16n8k16.row.col.f32.bf16.bf16.f32 "
                 "{%0,%1,%2,%3}, {%4,%5,%6,%7}, {%8,%9}, {%0,%1,%2,%3};"
                 : "+f"(d[0]), "+f"(d[1]), "+f"(d[2]), "+f"(d[3])
                 : "r"(a[0]), "r"(a[1]), "r"(a[2]), "r"(a[3]),
                   "r"(b[0]), "r"(b[1]));
}

// ===========================================================================
// Prep: split W into chunked smem-image layout
// ===========================================================================
__global__ void prep_W(const float* __restrict__ W, uint2* __restrict__ dst, int F) {
    int i = blockIdx.x * blockDim.x + threadIdx.x;
    int total = (F / 32) * 1024;
    if (i >= total) return;
    int chunk = i >> 10;
    int idx   = i & 1023;
    int nn = idx & 63;
    int kp = idx >> 6;
    int k  = chunk * 32 + kp * 2;
    float w0 = W[(size_t)k * 64 + nn];
    float w1 = W[(size_t)(k + 1) * 64 + nn];
    dst[i] = split_pack(w0, w1);
}

// ===========================================================================
// Tensor-core GEMM, double-buffered staging + register prefetch.
// 256 threads; block tile 128x64; warp tile 32x32; one sync per k-chunk.
// Dynamic smem: ws[2][64*20] + xs[2][128*20] uint2 = 60 KB.
// ===========================================================================
template<int F>
__global__ __launch_bounds__(256, 2) void gemm_bf16x3(const float* __restrict__ x,
                                                      const uint2* __restrict__ Wsp,
                                                      float* __restrict__ out, int n) {
    constexpr int NC = F / 32;
    extern __shared__ uint2 smbuf[];
    uint2* wsb[2] = { smbuf,            smbuf + 64 * 20 };
    uint2* xsb[2] = { smbuf + 2 * 64 * 20, smbuf + 2 * 64 * 20 + 128 * 20 };

    const int t    = threadIdx.x;
    const int lane = t & 31;
    const int wid  = t >> 5;
    const int wm   = wid >> 1;
    const int wn   = wid & 1;
    const int tig  = lane & 3;
    const int gid  = lane >> 2;
    const int row0 = blockIdx.x * 128;

    float2 xreg[8];
    uint2  wreg[4];

    auto ldg_chunk = [&](int c) {
        const uint2* src = Wsp + c * 1024;
        #pragma unroll
        for (int j = 0; j < 4; j++) wreg[j] = __ldg(src + j * 256 + t);
        #pragma unroll
        for (int j = 0; j < 8; j++) {
            int idx = j * 256 + t;
            int r   = idx >> 4;
            int kp  = idx & 15;
            int grow = row0 + r;
            xreg[j] = (grow < n)
                ? *(const float2*)(x + (size_t)grow * F + c * 32 + kp * 2)
                : make_float2(0.f, 0.f);
        }
    };
    auto sts_chunk = [&](int b) {
        #pragma unroll
        for (int j = 0; j < 4; j++) {
            int idx = j * 256 + t;
            wsb[b][(idx & 63) * 20 + (idx >> 6)] = wreg[j];
        }
        #pragma unroll
        for (int j = 0; j < 8; j++) {
            int idx = j * 256 + t;
            xsb[b][(idx >> 4) * 20 + (idx & 15)] = split_pack(xreg[j].x, xreg[j].y);
        }
    };

    float acc[2][4][4];
    #pragma unroll
    for (int mt = 0; mt < 2; mt++)
        #pragma unroll
        for (int nt = 0; nt < 4; nt++)
            #pragma unroll
            for (int q = 0; q < 4; q++) acc[mt][nt][q] = 0.f;

    // prologue
    ldg_chunk(0);
    sts_chunk(0);
    if (NC > 1) ldg_chunk(1);
    __syncthreads();

    #pragma unroll
    for (int c = 0; c < NC; c++) {
        if (c + 1 < NC) sts_chunk((c + 1) & 1);   // regs hold chunk c+1
        if (c + 2 < NC) ldg_chunk(c + 2);         // hidden behind compute

        const uint2* xs = xsb[c & 1];
        const uint2* ws = wsb[c & 1];

        #pragma unroll
        for (int ks = 0; ks < 2; ks++) {
            const int p0 = ks * 8 + tig;
            const int p1 = p0 + 4;

            uint32_t ah[2][4], al[2][4];
            #pragma unroll
            for (int mt = 0; mt < 2; mt++) {
                int r0 = wm * 32 + mt * 16 + gid;
                uint2 qa0 = xs[r0 * 20 + p0];
                uint2 qa1 = xs[(r0 + 8) * 20 + p0];
                uint2 qa2 = xs[r0 * 20 + p1];
                uint2 qa3 = xs[(r0 + 8) * 20 + p1];
                ah[mt][0] = qa0.x; ah[mt][1] = qa1.x; ah[mt][2] = qa2.x; ah[mt][3] = qa3.x;
                al[mt][0] = qa0.y; al[mt][1] = qa1.y; al[mt][2] = qa2.y; al[mt][3] = qa3.y;
            }

            #pragma unroll
            for (int nt = 0; nt < 4; nt++) {
                int nn = wn * 32 + nt * 8 + gid;
                uint2 qb0 = ws[nn * 20 + p0];
                uint2 qb1 = ws[nn * 20 + p1];
                uint32_t bh[2] = {qb0.x, qb1.x};
                uint32_t bl[2] = {qb0.y, qb1.y};
                #pragma unroll
                for (int mt = 0; mt < 2; mt++) {
                    mma_bf16(acc[mt][nt], ah[mt], bh);
                    mma_bf16(acc[mt][nt], al[mt], bh);
                    mma_bf16(acc[mt][nt], ah[mt], bl);
                }
            }
        }
        __syncthreads();
    }

    // Epilogue
    #pragma unroll
    for (int mt = 0; mt < 2; mt++) {
        #pragma unroll
        for (int half = 0; half < 2; half++) {
            int grow = row0 + wm * 32 + mt * 16 + gid + half * 8;
            if (grow < n) {
                float* o = out + (size_t)grow * D_MP + wn * 32 + tig * 2;
                #pragma unroll
                for (int nt = 0; nt < 4; nt++) {
                    float2 v = half ? make_float2(acc[mt][nt][2], acc[mt][nt][3])
                                    : make_float2(acc[mt][nt][0], acc[mt][nt][1]);
                    *(float2*)(o + nt * 8) = v;
                }
            }
        }
    }
}

// ===========================================================================
// CSR build
// ===========================================================================
__global__ void hist_dual(const int* __restrict__ rowA, const int* __restrict__ rowP,
                          int* __restrict__ cntA, int* __restrict__ cntP) {
    int i = blockIdx.x * blockDim.x + threadIdx.x;
    if (i < E_NNZ) {
        atomicAdd(&cntA[rowA[i]], 1);
    } else if (i < 2 * E_NNZ) {
        atomicAdd(&cntP[rowP[i - E_NNZ]], 1);
    }
}

#define SCAN_CHUNK 2048

__global__ void scan_pass1_dual(const int* __restrict__ cntA, int* __restrict__ bsA, int nA,
                                const int* __restrict__ cntP, int* __restrict__ bsP, int nP,
                                int nbA) {
    __shared__ int sh[256];
    const int* cnt = (blockIdx.x < nbA) ? cntA : cntP;
    int*       bs  = (blockIdx.x < nbA) ? bsA  : bsP;
    int        n   = (blockIdx.x < nbA) ? nA   : nP;
    int        blk = (blockIdx.x < nbA) ? blockIdx.x : blockIdx.x - nbA;
    int base = blk * SCAN_CHUNK;
    int t = threadIdx.x;
    int s = 0;
    #pragma unroll
    for (int j = 0; j < 8; j++) {
        int i = base + t * 8 + j;
        if (i < n) s += cnt[i];
    }
    sh[t] = s;
    __syncthreads();
    for (int off = 128; off > 0; off >>= 1) {
        if (t < off) sh[t] += sh[t + off];
        __syncthreads();
    }
    if (t == 0) bs[blk] = sh[0];
}

__global__ void scan_pass2_dual(int* __restrict__ bsA, int nbA,
                                int* __restrict__ bsP, int nbP) {
    __shared__ int sh[128];
    int* bs = blockIdx.x ? bsP : bsA;
    int nb  = blockIdx.x ? nbP : nbA;
    int t = threadIdx.x;
    int v = (t < nb) ? bs[t] : 0;
    sh[t] = v;
    __syncthreads();
    for (int off = 1; off < 128; off <<= 1) {
        int xx = (t >= off) ? sh[t - off] : 0;
        __syncthreads();
        sh[t] += xx;
        __syncthreads();
    }
    if (t < nb) bs[t] = sh[t] - v;
}

__global__ void scan_pass3_dual(const int* __restrict__ cntA, const int* __restrict__ bsA,
                                int* __restrict__ ptrA, int nA,
                                const int* __restrict__ cntP, const int* __restrict__ bsP,
                                int* __restrict__ ptrP, int nP, int nbA) {
    __shared__ int sh[256];
    const int* cnt = (blockIdx.x < nbA) ? cntA : cntP;
    const int* bs  = (blockIdx.x < nbA) ? bsA  : bsP;
    int*       ptr = (blockIdx.x < nbA) ? ptrA : ptrP;
    int        n   = (blockIdx.x < nbA) ? nA   : nP;
    int        blk = (blockIdx.x < nbA) ? blockIdx.x : blockIdx.x - nbA;
    int base = blk * SCAN_CHUNK;
    int t = threadIdx.x;
    int v[8];
    int s = 0;
    #pragma unroll
    for (int j = 0; j < 8; j++) {
        int i = base + t * 8 + j;
        v[j] = (i < n) ? cnt[i] : 0;
        s += v[j];
    }
    sh[t] = s;
    __syncthreads();
    for (int off = 1; off < 256; off <<= 1) {
        int xx = (t >= off) ? sh[t - off] : 0;
        __syncthreads();
        sh[t] += xx;
        __syncthreads();
    }
    int ex = sh[t] - s + bs[blk];
    #pragma unroll
    for (int j = 0; j < 8; j++) {
        int i = base + t * 8 + j;
        if (i < n) {
            ptr[i] = ex;
            ex += v[j];
            if (i == n - 1) ptr[n] = ex;
        }
    }
}

__global__ void scatter_dual(const int* __restrict__ rowA, const int* __restrict__ colA,
                             const float* __restrict__ valA,
                             const int* __restrict__ ptrA, int* __restrict__ curA,
                             int* __restrict__ ccolA, float* __restrict__ cvalA,
                             const int* __restrict__ rowP, const int* __restrict__ colP,
                             const float* __restrict__ valP,
                             const int* __restrict__ ptrP, int* __restrict__ curP,
                             int* __restrict__ ccolP, float* __restrict__ cvalP) {
    int i = blockIdx.x * blockDim.x + threadIdx.x;
    if (i < E_NNZ) {
        int r = rowA[i];
        int p = ptrA[r] + atomicAdd(&curA[r], 1);
        ccolA[p] = colA[i];
        cvalA[p] = valA[i];
    } else if (i < 2 * E_NNZ) {
        int j = i - E_NNZ;
        int r = rowP[j];
        int p = ptrP[r] + atomicAdd(&curP[r], 1);
        ccolP[p] = colP[j];
        cvalP[p] = valP[j];
    }
}

// ===========================================================================
// CSR SpMM: warp per row, 2-way unrolled per 16-lane half (R8 config)
// ===========================================================================
__global__ void spmm_csr_kernel(const int* __restrict__ ptr,
                                const int* __restrict__ ccol,
                                const float* __restrict__ cval,
                                const float* __restrict__ z,
                                float* __restrict__ out, int nrows) {
    int w = (blockIdx.x * blockDim.x + threadIdx.x) >> 5;
    if (w >= nrows) return;
    int lane = threadIdx.x & 31;
    int half = lane >> 4;
    int s    = lane & 15;

    int beg = ptr[w], end = ptr[w + 1];
    float4 acc0 = make_float4(0.f, 0.f, 0.f, 0.f);
    float4 acc1 = make_float4(0.f, 0.f, 0.f, 0.f);

    int e = beg + half;
    for (; e + 2 < end; e += 4) {
        int   c0 = __ldg(ccol + e);
        float v0 = __ldg(cval + e);
        int   c1 = __ldg(ccol + e + 2);
        float v1 = __ldg(cval + e + 2);
        float4 z0 = __ldg((const float4*)(z + (size_t)c0 * D_MP) + s);
        float4 z1 = __ldg((const float4*)(z + (size_t)c1 * D_MP) + s);
        acc0.x = fmaf(v0, z0.x, acc0.x);
        acc0.y = fmaf(v0, z0.y, acc0.y);
        acc0.z = fmaf(v0, z0.z, acc0.z);
        acc0.w = fmaf(v0, z0.w, acc0.w);
        acc1.x = fmaf(v1, z1.x, acc1.x);
        acc1.y = fmaf(v1, z1.y, acc1.y);
        acc1.z = fmaf(v1, z1.z, acc1.z);
        acc1.w = fmaf(v1, z1.w, acc1.w);
    }
    if (e < end) {
        int   c = __ldg(ccol + e);
        float v = __ldg(cval + e);
        float4 zv = __ldg((const float4*)(z + (size_t)c * D_MP) + s);
        acc0.x = fmaf(v, zv.x, acc0.x);
        acc0.y = fmaf(v, zv.y, acc0.y);
        acc0.z = fmaf(v, zv.z, acc0.z);
        acc0.w = fmaf(v, zv.w, acc0.w);
    }
    acc0.x += acc1.x; acc0.y += acc1.y; acc0.z += acc1.z; acc0.w += acc1.w;

    acc0.x += __shfl_xor_sync(0xffffffffu, acc0.x, 16);
    acc0.y += __shfl_xor_sync(0xffffffffu, acc0.y, 16);
    acc0.z += __shfl_xor_sync(0xffffffffu, acc0.z, 16);
    acc0.w += __shfl_xor_sync(0xffffffffu, acc0.w, 16);
    if (half == 0)
        *((float4*)(out + (size_t)w * D_MP) + s) = acc0;
}

// ===========================================================================
// Launch
// ===========================================================================
extern "C" void kernel_launch(void* const* d_in, const int* in_sizes, int n_in,
                              void* d_out, int out_size) {
    const float* x_paper  = (const float*)d_in[0];
    const float* x_author = (const float*)d_in[1];
    const float* W_paper  = (const float*)d_in[2];
    const float* W_author = (const float*)d_in[3];
    const int*   pa_row   = (const int*)  d_in[4];
    const int*   pa_col   = (const int*)  d_in[5];
    const float* pa_val   = (const float*)d_in[6];
    const int*   ap_row   = (const int*)  d_in[7];
    const int*   ap_col   = (const int*)  d_in[8];
    const float* ap_val   = (const float*)d_in[9];

    float* out       = (float*)d_out;
    float* out_pap   = out;
    float* out_papap = out + (size_t)N_P * D_MP;
    float* out_apa   = out + (size_t)2 * N_P * D_MP;

    float *bufP, *bufA1, *bufA2;
    uint2 *WspP, *WspA;
    int *pa_ptr, *ap_ptr, *pa_ccol, *ap_ccol, *cnt, *bsumA, *bsumP;
    float *pa_cval, *ap_cval;
    cudaGetSymbolAddress((void**)&bufP,    g_bufP);
    cudaGetSymbolAddress((void**)&bufA1,   g_bufA1);
    cudaGetSymbolAddress((void**)&bufA2,   g_bufA2);
    cudaGetSymbolAddress((void**)&WspP,    g_WsplitP);
    cudaGetSymbolAddress((void**)&WspA,    g_WsplitA);
    cudaGetSymbolAddress((void**)&pa_ptr,  g_pa_ptr);
    cudaGetSymbolAddress((void**)&ap_ptr,  g_ap_ptr);
    cudaGetSymbolAddress((void**)&pa_ccol, g_pa_ccol);
    cudaGetSymbolAddress((void**)&pa_cval, g_pa_cval);
    cudaGetSymbolAddress((void**)&ap_ccol, g_ap_ccol);
    cudaGetSymbolAddress((void**)&ap_cval, g_ap_cval);
    cudaGetSymbolAddress((void**)&cnt,     g_cnt);
    cudaGetSymbolAddress((void**)&bsumA,   g_bsumA);
    cudaGetSymbolAddress((void**)&bsumP,   g_bsumP);

    int* cntA = cnt;
    int* curA = cnt + N_A;
    int* cntP = cnt + 2 * N_A;
    int* curP = cnt + 2 * N_A + N_P;

    const int GEMM_SMEM = (2 * 64 * 20 + 2 * 128 * 20) * (int)sizeof(uint2);  // 61440
    cudaFuncSetAttribute(gemm_bf16x3<F_P>, cudaFuncAttributeMaxDynamicSharedMemorySize, GEMM_SMEM);
    cudaFuncSetAttribute(gemm_bf16x3<F_A>, cudaFuncAttributeMaxDynamicSharedMemorySize, GEMM_SMEM);

    cudaMemsetAsync(cnt, 0, (size_t)2 * (N_P + N_A) * sizeof(int));

    const int HB = 256;
    const int dgrid = (2 * E_NNZ + HB - 1) / HB;
    const int nbA = (N_A + SCAN_CHUNK - 1) / SCAN_CHUNK;
    const int nbP = (N_P + SCAN_CHUNK - 1) / SCAN_CHUNK;

    // node order: capture slot (4th kernel, idx 3) = gemm P
    hist_dual<<<dgrid, HB>>>(pa_row, ap_row, cntA, cntP);                          // 0
    prep_W<<<(F_P / 32 * 1024 + 255) / 256, 256>>>(W_paper,  WspP, F_P);           // 1
    prep_W<<<(F_A / 32 * 1024 + 255) / 256, 256>>>(W_author, WspA, F_A);           // 2
    gemm_bf16x3<F_P><<<(N_P + 127) / 128, 256, GEMM_SMEM>>>(x_paper,  WspP, bufP,  N_P); // 3
    gemm_bf16x3<F_A><<<(N_A + 127) / 128, 256, GEMM_SMEM>>>(x_author, WspA, bufA1, N_A); // 4
    scan_pass1_dual<<<nbA + nbP, 256>>>(cntA, bsumA, N_A, cntP, bsumP, N_P, nbA);  // 5
    scan_pass2_dual<<<2, 128>>>(bsumA, nbA, bsumP, nbP);                           // 6
    scan_pass3_dual<<<nbA + nbP, 256>>>(cntA, bsumA, pa_ptr, N_A,
                                        cntP, bsumP, ap_ptr, N_P, nbA);            // 7
    scatter_dual<<<dgrid, HB>>>(pa_row, pa_col, pa_val, pa_ptr, curA, pa_ccol, pa_cval,
                                ap_row, ap_col, ap_val, ap_ptr, curP, ap_ccol, ap_cval); // 8

    auto sblocks = [](int nrows) { return (nrows * 32 + 255) / 256; };

    // P-A-P
    spmm_csr_kernel<<<sblocks(N_A), 256>>>(pa_ptr, pa_ccol, pa_cval, bufP,  bufA2,   N_A);
    spmm_csr_kernel<<<sblocks(N_P), 256>>>(ap_ptr, ap_ccol, ap_cval, bufA2, out_pap, N_P);
    // P-A-P-A-P
    spmm_csr_kernel<<<sblocks(N_A), 256>>>(pa_ptr, pa_ccol, pa_cval, out_pap, bufA2,     N_A);
    spmm_csr_kernel<<<sblocks(N_P), 256>>>(ap_ptr, ap_ccol, ap_cval, bufA2,   out_papap, N_P);
    // A-P-A
    spmm_csr_kernel<<<sblocks(N_P), 256>>>(ap_ptr, ap_ccol, ap_cval, bufA1, bufP,    N_P);
    spmm_csr_kernel<<<sblocks(N_A), 256>>>(pa_ptr, pa_ccol, pa_cval, bufP,  out_apa, N_A);
}

// round 11
// speedup vs baseline: 1.2963x; 1.0696x over previous
#include <cuda_runtime.h>
#include <cuda_bf16.h>
#include <cstdint>

#define N_P   200000
#define N_A   100000
#define D_MP  64
#define E_NNZ 1200000
#define F_P   256
#define F_A   128

// ===========================================================================
// Static scratch
// ===========================================================================
__device__ __align__(16) float g_bufP [(size_t)N_P * D_MP];   // zp
__device__ __align__(16) float g_bufG [(size_t)N_P * D_MP];   // g (apa chain)
__device__ __align__(16) float g_bufA1[(size_t)N_A * D_MP];   // za
__device__ __align__(16) float g_bufA2[(size_t)N_A * D_MP];   // h, later h2

// Pre-split W images (hi/lo bf16x2), chunked to match the GEMM smem image
__device__ __align__(16) uint2 g_WsplitP[(F_P / 32) * 1024];
__device__ __align__(16) uint2 g_WsplitA[(F_A / 32) * 1024];

// CSR scratch
__device__ int   g_pa_ptr[N_A + 1];
__device__ int   g_ap_ptr[N_P + 1];
__device__ int   g_pa_ccol[E_NNZ];
__device__ float g_pa_cval[E_NNZ];
__device__ int   g_ap_ccol[E_NNZ];
__device__ float g_ap_cval[E_NNZ];
__device__ int   g_cnt[2 * (N_P + N_A)];
__device__ int   g_bsumA[128];
__device__ int   g_bsumP[128];

// ===========================================================================
// bf16 split helpers
// ===========================================================================
__device__ __forceinline__ uint2 split_pack(float a, float b) {
    float fa = __bfloat162float(__float2bfloat16_rn(a));
    float fb = __bfloat162float(__float2bfloat16_rn(b));
    uint32_t hi, lo;
    asm("cvt.rn.bf16x2.f32 %0, %1, %2;" : "=r"(hi) : "f"(fb), "f"(fa));
    asm("cvt.rn.bf16x2.f32 %0, %1, %2;" : "=r"(lo) : "f"(b - fb), "f"(a - fa));
    return make_uint2(hi, lo);
}

__device__ __forceinline__ void mma_bf16(float* d, const uint32_t* a, const uint32_t* b) {
    asm volatile("mma.sync.aligned.m16n8k16.row.col.f32.bf16.bf16.f32 "
                 "{%0,%1,%2,%3}, {%4,%5,%6,%7}, {%8,%9}, {%0,%1,%2,%3};"
                 : "+f"(d[0]), "+f"(d[1]), "+f"(d[2]), "+f"(d[3])
                 : "r"(a[0]), "r"(a[1]), "r"(a[2]), "r"(a[3]),
                   "r"(b[0]), "r"(b[1]));
}

// ===========================================================================
// Prep: split W into chunked smem-image layout
// ===========================================================================
__global__ void prep_W(const float* __restrict__ W, uint2* __restrict__ dst, int F) {
    int i = blockIdx.x * blockDim.x + threadIdx.x;
    int total = (F / 32) * 1024;
    if (i >= total) return;
    int chunk = i >> 10;
    int idx   = i & 1023;
    int nn = idx & 63;
    int kp = idx >> 6;
    int k  = chunk * 32 + kp * 2;
    float w0 = W[(size_t)k * 64 + nn];
    float w1 = W[(size_t)(k + 1) * 64 + nn];
    dst[i] = split_pack(w0, w1);
}

// ===========================================================================
// Tensor-core GEMM, double-buffered staging + register prefetch (R10 best)
// ===========================================================================
template<int F>
__global__ __launch_bounds__(256, 2) void gemm_bf16x3(const float* __restrict__ x,
                                                      const uint2* __restrict__ Wsp,
                                                      float* __restrict__ out, int n) {
    constexpr int NC = F / 32;
    extern __shared__ uint2 smbuf[];
    uint2* wsb[2] = { smbuf,            smbuf + 64 * 20 };
    uint2* xsb[2] = { smbuf + 2 * 64 * 20, smbuf + 2 * 64 * 20 + 128 * 20 };

    const int t    = threadIdx.x;
    const int lane = t & 31;
    const int wid  = t >> 5;
    const int wm   = wid >> 1;
    const int wn   = wid & 1;
    const int tig  = lane & 3;
    const int gid  = lane >> 2;
    const int row0 = blockIdx.x * 128;

    float2 xreg[8];
    uint2  wreg[4];

    auto ldg_chunk = [&](int c) {
        const uint2* src = Wsp + c * 1024;
        #pragma unroll
        for (int j = 0; j < 4; j++) wreg[j] = __ldg(src + j * 256 + t);
        #pragma unroll
        for (int j = 0; j < 8; j++) {
            int idx = j * 256 + t;
            int r   = idx >> 4;
            int kp  = idx & 15;
            int grow = row0 + r;
            xreg[j] = (grow < n)
                ? *(const float2*)(x + (size_t)grow * F + c * 32 + kp * 2)
                : make_float2(0.f, 0.f);
        }
    };
    auto sts_chunk = [&](int b) {
        #pragma unroll
        for (int j = 0; j < 4; j++) {
            int idx = j * 256 + t;
            wsb[b][(idx & 63) * 20 + (idx >> 6)] = wreg[j];
        }
        #pragma unroll
        for (int j = 0; j < 8; j++) {
            int idx = j * 256 + t;
            xsb[b][(idx >> 4) * 20 + (idx & 15)] = split_pack(xreg[j].x, xreg[j].y);
        }
    };

    float acc[2][4][4];
    #pragma unroll
    for (int mt = 0; mt < 2; mt++)
        #pragma unroll
        for (int nt = 0; nt < 4; nt++)
            #pragma unroll
            for (int q = 0; q < 4; q++) acc[mt][nt][q] = 0.f;

    ldg_chunk(0);
    sts_chunk(0);
    if (NC > 1) ldg_chunk(1);
    __syncthreads();

    #pragma unroll
    for (int c = 0; c < NC; c++) {
        if (c + 1 < NC) sts_chunk((c + 1) & 1);
        if (c + 2 < NC) ldg_chunk(c + 2);

        const uint2* xs = xsb[c & 1];
        const uint2* ws = wsb[c & 1];

        #pragma unroll
        for (int ks = 0; ks < 2; ks++) {
            const int p0 = ks * 8 + tig;
            const int p1 = p0 + 4;

            uint32_t ah[2][4], al[2][4];
            #pragma unroll
            for (int mt = 0; mt < 2; mt++) {
                int r0 = wm * 32 + mt * 16 + gid;
                uint2 qa0 = xs[r0 * 20 + p0];
                uint2 qa1 = xs[(r0 + 8) * 20 + p0];
                uint2 qa2 = xs[r0 * 20 + p1];
                uint2 qa3 = xs[(r0 + 8) * 20 + p1];
                ah[mt][0] = qa0.x; ah[mt][1] = qa1.x; ah[mt][2] = qa2.x; ah[mt][3] = qa3.x;
                al[mt][0] = qa0.y; al[mt][1] = qa1.y; al[mt][2] = qa2.y; al[mt][3] = qa3.y;
            }

            #pragma unroll
            for (int nt = 0; nt < 4; nt++) {
                int nn = wn * 32 + nt * 8 + gid;
                uint2 qb0 = ws[nn * 20 + p0];
                uint2 qb1 = ws[nn * 20 + p1];
                uint32_t bh[2] = {qb0.x, qb1.x};
                uint32_t bl[2] = {qb0.y, qb1.y};
                #pragma unroll
                for (int mt = 0; mt < 2; mt++) {
                    mma_bf16(acc[mt][nt], ah[mt], bh);
                    mma_bf16(acc[mt][nt], al[mt], bh);
                    mma_bf16(acc[mt][nt], ah[mt], bl);
                }
            }
        }
        __syncthreads();
    }

    #pragma unroll
    for (int mt = 0; mt < 2; mt++) {
        #pragma unroll
        for (int half = 0; half < 2; half++) {
            int grow = row0 + wm * 32 + mt * 16 + gid + half * 8;
            if (grow < n) {
                float* o = out + (size_t)grow * D_MP + wn * 32 + tig * 2;
                #pragma unroll
                for (int nt = 0; nt < 4; nt++) {
                    float2 v = half ? make_float2(acc[mt][nt][2], acc[mt][nt][3])
                                    : make_float2(acc[mt][nt][0], acc[mt][nt][1]);
                    *(float2*)(o + nt * 8) = v;
                }
            }
        }
    }
}

// ===========================================================================
// CSR build (unchanged)
// ===========================================================================
__global__ void hist_dual(const int* __restrict__ rowA, const int* __restrict__ rowP,
                          int* __restrict__ cntA, int* __restrict__ cntP) {
    int i = blockIdx.x * blockDim.x + threadIdx.x;
    if (i < E_NNZ) {
        atomicAdd(&cntA[rowA[i]], 1);
    } else if (i < 2 * E_NNZ) {
        atomicAdd(&cntP[rowP[i - E_NNZ]], 1);
    }
}

#define SCAN_CHUNK 2048

__global__ void scan_pass1_dual(const int* __restrict__ cntA, int* __restrict__ bsA, int nA,
                                const int* __restrict__ cntP, int* __restrict__ bsP, int nP,
                                int nbA) {
    __shared__ int sh[256];
    const int* cnt = (blockIdx.x < nbA) ? cntA : cntP;
    int*       bs  = (blockIdx.x < nbA) ? bsA  : bsP;
    int        n   = (blockIdx.x < nbA) ? nA   : nP;
    int        blk = (blockIdx.x < nbA) ? blockIdx.x : blockIdx.x - nbA;
    int base = blk * SCAN_CHUNK;
    int t = threadIdx.x;
    int s = 0;
    #pragma unroll
    for (int j = 0; j < 8; j++) {
        int i = base + t * 8 + j;
        if (i < n) s += cnt[i];
    }
    sh[t] = s;
    __syncthreads();
    for (int off = 128; off > 0; off >>= 1) {
        if (t < off) sh[t] += sh[t + off];
        __syncthreads();
    }
    if (t == 0) bs[blk] = sh[0];
}

__global__ void scan_pass2_dual(int* __restrict__ bsA, int nbA,
                                int* __restrict__ bsP, int nbP) {
    __shared__ int sh[128];
    int* bs = blockIdx.x ? bsP : bsA;
    int nb  = blockIdx.x ? nbP : nbA;
    int t = threadIdx.x;
    int v = (t < nb) ? bs[t] : 0;
    sh[t] = v;
    __syncthreads();
    for (int off = 1; off < 128; off <<= 1) {
        int xx = (t >= off) ? sh[t - off] : 0;
        __syncthreads();
        sh[t] += xx;
        __syncthreads();
    }
    if (t < nb) bs[t] = sh[t] - v;
}

__global__ void scan_pass3_dual(const int* __restrict__ cntA, const int* __restrict__ bsA,
                                int* __restrict__ ptrA, int nA,
                                const int* __restrict__ cntP, const int* __restrict__ bsP,
                                int* __restrict__ ptrP, int nP, int nbA) {
    __shared__ int sh[256];
    const int* cnt = (blockIdx.x < nbA) ? cntA : cntP;
    const int* bs  = (blockIdx.x < nbA) ? bsA  : bsP;
    int*       ptr = (blockIdx.x < nbA) ? ptrA : ptrP;
    int        n   = (blockIdx.x < nbA) ? nA   : nP;
    int        blk = (blockIdx.x < nbA) ? blockIdx.x : blockIdx.x - nbA;
    int base = blk * SCAN_CHUNK;
    int t = threadIdx.x;
    int v[8];
    int s = 0;
    #pragma unroll
    for (int j = 0; j < 8; j++) {
        int i = base + t * 8 + j;
        v[j] = (i < n) ? cnt[i] : 0;
        s += v[j];
    }
    sh[t] = s;
    __syncthreads();
    for (int off = 1; off < 256; off <<= 1) {
        int xx = (t >= off) ? sh[t - off] : 0;
        __syncthreads();
        sh[t] += xx;
        __syncthreads();
    }
    int ex = sh[t] - s + bs[blk];
    #pragma unroll
    for (int j = 0; j < 8; j++) {
        int i = base + t * 8 + j;
        if (i < n) {
            ptr[i] = ex;
            ex += v[j];
            if (i == n - 1) ptr[n] = ex;
        }
    }
}

__global__ void scatter_dual(const int* __restrict__ rowA, const int* __restrict__ colA,
                             const float* __restrict__ valA,
                             const int* __restrict__ ptrA, int* __restrict__ curA,
                             int* __restrict__ ccolA, float* __restrict__ cvalA,
                             const int* __restrict__ rowP, const int* __restrict__ colP,
                             const float* __restrict__ valP,
                             const int* __restrict__ ptrP, int* __restrict__ curP,
                             int* __restrict__ ccolP, float* __restrict__ cvalP) {
    int i = blockIdx.x * blockDim.x + threadIdx.x;
    if (i < E_NNZ) {
        int r = rowA[i];
        int p = ptrA[r] + atomicAdd(&curA[r], 1);
        ccolA[p] = colA[i];
        cvalA[p] = valA[i];
    } else if (i < 2 * E_NNZ) {
        int j = i - E_NNZ;
        int r = rowP[j];
        int p = ptrP[r] + atomicAdd(&curP[r], 1);
        ccolP[p] = colP[j];
        cvalP[p] = valP[j];
    }
}

// ===========================================================================
// CSR SpMM (R10/R8 config)
// ===========================================================================
__global__ void spmm_csr_kernel(const int* __restrict__ ptr,
                                const int* __restrict__ ccol,
                                const float* __restrict__ cval,
                                const float* __restrict__ z,
                                float* __restrict__ out, int nrows) {
    int w = (blockIdx.x * blockDim.x + threadIdx.x) >> 5;
    if (w >= nrows) return;
    int lane = threadIdx.x & 31;
    int half = lane >> 4;
    int s    = lane & 15;

    int beg = ptr[w], end = ptr[w + 1];
    float4 acc0 = make_float4(0.f, 0.f, 0.f, 0.f);
    float4 acc1 = make_float4(0.f, 0.f, 0.f, 0.f);

    int e = beg + half;
    for (; e + 2 < end; e += 4) {
        int   c0 = __ldg(ccol + e);
        float v0 = __ldg(cval + e);
        int   c1 = __ldg(ccol + e + 2);
        float v1 = __ldg(cval + e + 2);
        float4 z0 = __ldg((const float4*)(z + (size_t)c0 * D_MP) + s);
        float4 z1 = __ldg((const float4*)(z + (size_t)c1 * D_MP) + s);
        acc0.x = fmaf(v0, z0.x, acc0.x);
        acc0.y = fmaf(v0, z0.y, acc0.y);
        acc0.z = fmaf(v0, z0.z, acc0.z);
        acc0.w = fmaf(v0, z0.w, acc0.w);
        acc1.x = fmaf(v1, z1.x, acc1.x);
        acc1.y = fmaf(v1, z1.y, acc1.y);
        acc1.z = fmaf(v1, z1.z, acc1.z);
        acc1.w = fmaf(v1, z1.w, acc1.w);
    }
    if (e < end) {
        int   c = __ldg(ccol + e);
        float v = __ldg(cval + e);
        float4 zv = __ldg((const float4*)(z + (size_t)c * D_MP) + s);
        acc0.x = fmaf(v, zv.x, acc0.x);
        acc0.y = fmaf(v, zv.y, acc0.y);
        acc0.z = fmaf(v, zv.z, acc0.z);
        acc0.w = fmaf(v, zv.w, acc0.w);
    }
    acc0.x += acc1.x; acc0.y += acc1.y; acc0.z += acc1.z; acc0.w += acc1.w;

    acc0.x += __shfl_xor_sync(0xffffffffu, acc0.x, 16);
    acc0.y += __shfl_xor_sync(0xffffffffu, acc0.y, 16);
    acc0.z += __shfl_xor_sync(0xffffffffu, acc0.z, 16);
    acc0.w += __shfl_xor_sync(0xffffffffu, acc0.w, 16);
    if (half == 0)
        *((float4*)(out + (size_t)w * D_MP) + s) = acc0;
}

// ===========================================================================
// Launch — multi-stream overlap: s2 = CSR build, s3 = gemm A + A-P-A chain
// ===========================================================================
extern "C" void kernel_launch(void* const* d_in, const int* in_sizes, int n_in,
                              void* d_out, int out_size) {
    const float* x_paper  = (const float*)d_in[0];
    const float* x_author = (const float*)d_in[1];
    const float* W_paper  = (const float*)d_in[2];
    const float* W_author = (const float*)d_in[3];
    const int*   pa_row   = (const int*)  d_in[4];
    const int*   pa_col   = (const int*)  d_in[5];
    const float* pa_val   = (const float*)d_in[6];
    const int*   ap_row   = (const int*)  d_in[7];
    const int*   ap_col   = (const int*)  d_in[8];
    const float* ap_val   = (const float*)d_in[9];

    float* out       = (float*)d_out;
    float* out_pap   = out;
    float* out_papap = out + (size_t)N_P * D_MP;
    float* out_apa   = out + (size_t)2 * N_P * D_MP;

    float *bufP, *bufG, *bufA1, *bufA2;
    uint2 *WspP, *WspA;
    int *pa_ptr, *ap_ptr, *pa_ccol, *ap_ccol, *cnt, *bsumA, *bsumP;
    float *pa_cval, *ap_cval;
    cudaGetSymbolAddress((void**)&bufP,    g_bufP);
    cudaGetSymbolAddress((void**)&bufG,    g_bufG);
    cudaGetSymbolAddress((void**)&bufA1,   g_bufA1);
    cudaGetSymbolAddress((void**)&bufA2,   g_bufA2);
    cudaGetSymbolAddress((void**)&WspP,    g_WsplitP);
    cudaGetSymbolAddress((void**)&WspA,    g_WsplitA);
    cudaGetSymbolAddress((void**)&pa_ptr,  g_pa_ptr);
    cudaGetSymbolAddress((void**)&ap_ptr,  g_ap_ptr);
    cudaGetSymbolAddress((void**)&pa_ccol, g_pa_ccol);
    cudaGetSymbolAddress((void**)&pa_cval, g_pa_cval);
    cudaGetSymbolAddress((void**)&ap_ccol, g_ap_ccol);
    cudaGetSymbolAddress((void**)&ap_cval, g_ap_cval);
    cudaGetSymbolAddress((void**)&cnt,     g_cnt);
    cudaGetSymbolAddress((void**)&bsumA,   g_bsumA);
    cudaGetSymbolAddress((void**)&bsumP,   g_bsumP);

    int* cntA = cnt;
    int* curA = cnt + N_A;
    int* cntP = cnt + 2 * N_A;
    int* curP = cnt + 2 * N_A + N_P;

    // One-time stream/event setup (host resources only; no device memory)
    static cudaStream_t s2 = nullptr, s3 = nullptr;
    static cudaEvent_t eFork, eCsr, ePrep, eApa;
    if (s2 == nullptr) {
        cudaStreamCreateWithFlags(&s2, cudaStreamNonBlocking);
        cudaStreamCreateWithFlags(&s3, cudaStreamNonBlocking);
        cudaEventCreateWithFlags(&eFork, cudaEventDisableTiming);
        cudaEventCreateWithFlags(&eCsr,  cudaEventDisableTiming);
        cudaEventCreateWithFlags(&ePrep, cudaEventDisableTiming);
        cudaEventCreateWithFlags(&eApa,  cudaEventDisableTiming);
    }

    const int GEMM_SMEM = (2 * 64 * 20 + 2 * 128 * 20) * (int)sizeof(uint2);  // 61440
    cudaFuncSetAttribute(gemm_bf16x3<F_P>, cudaFuncAttributeMaxDynamicSharedMemorySize, GEMM_SMEM);
    cudaFuncSetAttribute(gemm_bf16x3<F_A>, cudaFuncAttributeMaxDynamicSharedMemorySize, GEMM_SMEM);

    const int HB = 256;
    const int dgrid = (2 * E_NNZ + HB - 1) / HB;
    const int nbA = (N_A + SCAN_CHUNK - 1) / SCAN_CHUNK;
    const int nbP = (N_P + SCAN_CHUNK - 1) / SCAN_CHUNK;
    auto sblocks = [](int nrows) { return (nrows * 32 + 255) / 256; };

    // ---- fork ----
    cudaEventRecord(eFork, 0);
    cudaStreamWaitEvent(s2, eFork, 0);
    cudaStreamWaitEvent(s3, eFork, 0);

    // ---- s2: CSR build (hidden under GEMMs) ----
    cudaMemsetAsync(cnt, 0, (size_t)2 * (N_P + N_A) * sizeof(int), s2);
    hist_dual<<<dgrid, HB, 0, s2>>>(pa_row, ap_row, cntA, cntP);
    scan_pass1_dual<<<nbA + nbP, 256, 0, s2>>>(cntA, bsumA, N_A, cntP, bsumP, N_P, nbA);
    scan_pass2_dual<<<2, 128, 0, s2>>>(bsumA, nbA, bsumP, nbP);
    scan_pass3_dual<<<nbA + nbP, 256, 0, s2>>>(cntA, bsumA, pa_ptr, N_A,
                                               cntP, bsumP, ap_ptr, N_P, nbA);
    scatter_dual<<<dgrid, HB, 0, s2>>>(pa_row, pa_col, pa_val, pa_ptr, curA, pa_ccol, pa_cval,
                                       ap_row, ap_col, ap_val, ap_ptr, curP, ap_ccol, ap_cval);
    cudaEventRecord(eCsr, s2);

    // ---- main: W prep + gemm P;  s3: gemm A ----
    prep_W<<<(F_P / 32 * 1024 + 255) / 256, 256>>>(W_paper,  WspP, F_P);
    prep_W<<<(F_A / 32 * 1024 + 255) / 256, 256>>>(W_author, WspA, F_A);
    cudaEventRecord(ePrep, 0);
    cudaStreamWaitEvent(s3, ePrep, 0);

    gemm_bf16x3<F_P><<<(N_P + 127) / 128, 256, GEMM_SMEM>>>(x_paper, WspP, bufP, N_P);
    gemm_bf16x3<F_A><<<(N_A + 127) / 128, 256, GEMM_SMEM, s3>>>(x_author, WspA, bufA1, N_A);

    // ---- main: P-A-P / P-A-P-A-P chains ----
    cudaStreamWaitEvent(0, eCsr, 0);
    spmm_csr_kernel<<<sblocks(N_A), 256>>>(pa_ptr, pa_ccol, pa_cval, bufP,    bufA2,     N_A); // h
    spmm_csr_kernel<<<sblocks(N_P), 256>>>(ap_ptr, ap_ccol, ap_cval, bufA2,   out_pap,   N_P); // pap
    spmm_csr_kernel<<<sblocks(N_A), 256>>>(pa_ptr, pa_ccol, pa_cval, out_pap, bufA2,     N_A); // h2
    spmm_csr_kernel<<<sblocks(N_P), 256>>>(ap_ptr, ap_ccol, ap_cval, bufA2,   out_papap, N_P); // papap

    // ---- s3: A-P-A chain (independent; uses bufG to avoid clobbering zp) ----
    cudaStreamWaitEvent(s3, eCsr, 0);
    spmm_csr_kernel<<<sblocks(N_P), 256, 0, s3>>>(ap_ptr, ap_ccol, ap_cval, bufA1, bufG,    N_P); // g
    spmm_csr_kernel<<<sblocks(N_A), 256, 0, s3>>>(pa_ptr, pa_ccol, pa_cval, bufG,  out_apa, N_A); // apa
    cudaEventRecord(eApa, s3);

    // ---- join ----
    cudaStreamWaitEvent(0, eApa, 0);
}